// round 11
// baseline (speedup 1.0000x reference)
#include <cuda_runtime.h>

#define NLAB   2047
#define NBATCH 2048

// Precomputed EXP of compact transition tables (gathered per launch, deterministic).
// eTup[n] = exp(transitions[parent(n), n, :, :])  (message n -> parent)
// eTdn[n] = exp(transitions[n, parent(n), :, :])  (message parent -> n)
__device__ float4 g_eTup[2048];
__device__ float4 g_eTdn[2048];

__global__ void prep_kernel(const float* __restrict__ trans) {
    int n = blockIdx.x * blockDim.x + threadIdx.x;
    if (n >= NLAB) return;
    if (n == 0) {
        g_eTup[0] = make_float4(1.f, 1.f, 1.f, 1.f);
        g_eTdn[0] = make_float4(1.f, 1.f, 1.f, 1.f);
        return;
    }
    int p = (n - 1) >> 1;
    const float4* t4 = reinterpret_cast<const float4*>(trans);
    float4 u = t4[(size_t)p * NLAB + n];
    float4 d = t4[(size_t)n * NLAB + p];
    g_eTup[n] = make_float4(__expf(u.x), __expf(u.y), __expf(u.z), __expf(u.w));
    g_eTdn[n] = make_float4(__expf(d.x), __expf(d.y), __expf(d.z), __expf(d.w));
}

__device__ __forceinline__ float2 f2add(float2 a, float2 b) {
    return make_float2(a.x + b.x, a.y + b.y);
}

// Both-destination-class logsumexp for one edge, sharing one exp.
__device__ __forceinline__ float2 lsepair2(float2 x, float4 eT) {
    float m  = fmaxf(x.x, x.y);
    float pd = __expf(fminf(x.x, x.y) - m);
    bool  f  = (x.x >= x.y);
    float a0 = f ? eT.x : eT.y, b0 = f ? eT.y : eT.x;
    float a1 = f ? eT.z : eT.w, b1 = f ? eT.w : eT.z;
    return make_float2(m + __logf(fmaf(pd, b0, a0)),
                       m + __logf(fmaf(pd, b1, a1)));
}

__device__ __forceinline__ float2 up_combine(float2 xl, float2 xr, float4 Tl, float4 Tr) {
    float2 a = lsepair2(xl, Tl);
    float2 b = lsepair2(xr, Tr);
    return make_float2(a.x + b.x, a.y + b.y);
}

__device__ __forceinline__ float lse2(float u, float v) {
    float m = fmaxf(u, v);
    return m + __logf(1.0f + __expf(fminf(u, v) - m));
}

__device__ __forceinline__ void emit2(float* __restrict__ orow, int n, float2 s) {
    float z = lse2(s.x, s.y);
    orow[n]        = s.x - z;
    orow[NLAB + n] = s.y - z;
}

__device__ __forceinline__ float2 ld_e(const float* __restrict__ er, int n) {
    return make_float2(er[n], er[NLAB + n]);
}

// ONE WARP = ONE BATCH ROW. 64-thread CTA = 2 independent warps/rows.
// Per-row warp-private smem: E (emissions, internal nodes 0..1022) and
// X (x = e+alpha up; morphs to t = e+beta down). 4*1024 float2 = 32 KB/CTA
// -> 6 CTAs/SM (12 independent warps). NO __syncthreads anywhere; levels are
// separated by __syncwarp only. Lane i owns nodes base+i+32k (coalesced).
__global__ void __launch_bounds__(64) crf_kernel(const float* __restrict__ em,
                                                 float* __restrict__ out) {
    __shared__ float2 SM[4096];

    const int w    = threadIdx.x >> 5;
    const int lane = threadIdx.x & 31;
    const int row  = blockIdx.x * 2 + w;
    const float* __restrict__ er = em + (size_t)row * (2 * NLAB);
    float* __restrict__ orow = out + (size_t)row * (2 * NLAB);
    float2* E = SM + w * 2048;
    float2* X = E + 1024;

    // ---- load internal emissions (coalesced; no dependency chain)
    #pragma unroll 4
    for (int k = 0; k < 32; ++k) {
        int n = lane + 32 * k;
        if (n < 1023) E[n] = ld_e(er, n);
    }

    // ---- up, leaf level: parents 511..1022 combine their two leaves
    #pragma unroll 4
    for (int k = 0; k < 16; ++k) {
        int p = 511 + lane + 32 * k;
        int c = 2 * p + 1;
        float2 a = up_combine(ld_e(er, c), ld_e(er, c + 1),
                              g_eTup[c], g_eTup[c + 1]);
        X[p] = f2add(E[p], a);
    }
    __syncwarp();

    // ---- up, levels with cnt >= 32 (pl = 8..5)
    #pragma unroll
    for (int pl = 8; pl >= 5; --pl) {
        const int base = (1 << pl) - 1;
        const int cnt  = 1 << pl;
        #pragma unroll 4
        for (int k = 0; k < cnt; k += 32) {
            int p = base + lane + k;
            int c = 2 * p + 1;
            float2 a = up_combine(X[c], X[c + 1], g_eTup[c], g_eTup[c + 1]);
            X[p] = f2add(E[p], a);
        }
        __syncwarp();
    }

    // ---- up, small levels (pl = 4..0)
    #pragma unroll
    for (int pl = 4; pl >= 0; --pl) {
        const int base = (1 << pl) - 1;
        const int cnt  = 1 << pl;
        if (lane < cnt) {
            int p = base + lane;
            int c = 2 * p + 1;
            float2 a = up_combine(X[c], X[c + 1], g_eTup[c], g_eTup[c + 1]);
            X[p] = f2add(E[p], a);
        }
        __syncwarp();
    }

    // ---- root: emit score (beta=0 -> score = x), then X[0] <- t = e
    if (lane == 0) {
        emit2(orow, 0, X[0]);
        X[0] = E[0];
    }
    __syncwarp();

    // ---- down, small levels (pl = 1..4): pull from parent's t
    #pragma unroll
    for (int pl = 1; pl <= 4; ++pl) {
        const int base = (1 << pl) - 1;
        const int cnt  = 1 << pl;
        if (lane < cnt) {
            int n = base + lane;
            float2 be = lsepair2(X[(n - 1) >> 1], g_eTdn[n]);
            emit2(orow, n, f2add(X[n], be));
            X[n] = f2add(E[n], be);
        }
        __syncwarp();
    }

    // ---- down, levels with cnt >= 32 (pl = 5..9)
    #pragma unroll
    for (int pl = 5; pl <= 9; ++pl) {
        const int base = (1 << pl) - 1;
        const int cnt  = 1 << pl;
        #pragma unroll 4
        for (int k = 0; k < cnt; k += 32) {
            int n = base + lane + k;
            float2 be = lsepair2(X[(n - 1) >> 1], g_eTdn[n]);
            emit2(orow, n, f2add(X[n], be));
            X[n] = f2add(E[n], be);
        }
        __syncwarp();
    }

    // ---- down, leaves 1023..2046: score = e + beta (alpha = 0)
    #pragma unroll 4
    for (int k = 0; k < 32; ++k) {
        int n = 1023 + lane + 32 * k;
        float2 be = lsepair2(X[(n - 1) >> 1], g_eTdn[n]);
        emit2(orow, n, f2add(ld_e(er, n), be));
    }
}

extern "C" void kernel_launch(void* const* d_in, const int* in_sizes, int n_in,
                              void* d_out, int out_size) {
    const float* em = (const float*)d_in[0];
    const float* tr = (const float*)d_in[1];
    if (n_in >= 2 && in_sizes[0] != NBATCH * 2 * NLAB) {
        em = (const float*)d_in[1];
        tr = (const float*)d_in[0];
    }
    prep_kernel<<<(NLAB + 255) / 256, 256>>>(tr);
    crf_kernel<<<NBATCH / 2, 64>>>(em, (float*)d_out);
}

// round 12
// speedup vs baseline: 1.2669x; 1.2669x over previous
#include <cuda_runtime.h>

#define NLAB   2047
#define NBATCH 2048
#define NTHR   128

// Precomputed EXP of compact transition tables (gathered per launch, deterministic).
// eTup[n] = exp(transitions[parent(n), n, :, :])  (message n -> parent)
// eTdn[n] = exp(transitions[n, parent(n), :, :])  (message parent -> n)
__device__ float4 g_eTup[2048];
__device__ float4 g_eTdn[2048];

__global__ void prep_kernel(const float* __restrict__ trans) {
    int n = blockIdx.x * blockDim.x + threadIdx.x;
    if (n >= NLAB) return;
    if (n == 0) {
        g_eTup[0] = make_float4(1.f, 1.f, 1.f, 1.f);
        g_eTdn[0] = make_float4(1.f, 1.f, 1.f, 1.f);
        return;
    }
    int p = (n - 1) >> 1;
    const float4* t4 = reinterpret_cast<const float4*>(trans);
    float4 u = t4[(size_t)p * NLAB + n];
    float4 d = t4[(size_t)n * NLAB + p];
    g_eTup[n] = make_float4(__expf(u.x), __expf(u.y), __expf(u.z), __expf(u.w));
    g_eTdn[n] = make_float4(__expf(d.x), __expf(d.y), __expf(d.z), __expf(d.w));
}

__device__ __forceinline__ float2 f2add(float2 a, float2 b) {
    return make_float2(a.x + b.x, a.y + b.y);
}

// Both-destination-class logsumexp for one edge, sharing one exp.
__device__ __forceinline__ float2 lsepair2(float2 x, float4 eT) {
    float m  = fmaxf(x.x, x.y);
    float pd = __expf(fminf(x.x, x.y) - m);
    bool  f  = (x.x >= x.y);
    float a0 = f ? eT.x : eT.y, b0 = f ? eT.y : eT.x;
    float a1 = f ? eT.z : eT.w, b1 = f ? eT.w : eT.z;
    return make_float2(m + __logf(fmaf(pd, b0, a0)),
                       m + __logf(fmaf(pd, b1, a1)));
}

__device__ __forceinline__ float2 up_combine(float2 xl, float2 xr, float4 Tl, float4 Tr) {
    float2 a = lsepair2(xl, Tl);
    float2 b = lsepair2(xr, Tr);
    return make_float2(a.x + b.x, a.y + b.y);
}

__device__ __forceinline__ float lse2(float u, float v) {
    float m = fmaxf(u, v);
    return m + __logf(1.0f + __expf(fminf(u, v) - m));
}

__device__ __forceinline__ void emit2(float* __restrict__ orow, int n, float2 s) {
    float z = lse2(s.x, s.y);
    orow[n]        = s.x - z;
    orow[NLAB + n] = s.y - z;
}

__device__ __forceinline__ float2 ld_e(const float* __restrict__ er, int n) {
    return make_float2(er[n], er[NLAB + n]);
}

// shared parent-exp for both children on the way down
#define PARENT_EXP(tp, m, pd, f) \
    float m  = fmaxf((tp).x, (tp).y); \
    float pd = __expf(fminf((tp).x, (tp).y) - m); \
    bool  f  = ((tp).x >= (tp).y);

__device__ __forceinline__ float2 child_be(float m, float pd, bool f, float4 eT) {
    float a0 = f ? eT.x : eT.y, b0 = f ? eT.y : eT.x;
    float a1 = f ? eT.z : eT.w, b1 = f ? eT.w : eT.z;
    return make_float2(m + __logf(fmaf(pd, b0, a0)),
                       m + __logf(fmaf(pd, b1, a1)));
}

// ONE batch row per 128-thread CTA. smem: E (emissions of internal nodes,
// morphing to t = e + beta on the way down) + A (alphas) = 16 KB/CTA
// -> 12 CTAs/SM (48 warps). Grid 2048 -> 1.15 waves. Barriers couple only
// 4 warps; 12 independent CTAs/SM hide each other's barrier waits.
__global__ void __launch_bounds__(NTHR, 12) crf_kernel(const float* __restrict__ em,
                                                       float* __restrict__ out) {
    __shared__ float2 E[1024], A[1024];

    const int tid = threadIdx.x;
    const size_t boff = (size_t)blockIdx.x * (2 * NLAB);
    const float* __restrict__ er = em + boff;
    float* __restrict__ orow = out + boff;

    // ---- load internal emissions (coalesced) + up leaf level fused:
    //      parents 511..1022 combine their two leaves (leaf alpha = 0)
    for (int n = tid; n < 1023; n += NTHR) E[n] = ld_e(er, n);
    #pragma unroll
    for (int k = 0; k < 4; ++k) {
        int p = 511 + tid + NTHR * k;
        int c = 2 * p + 1;
        A[p] = up_combine(ld_e(er, c), ld_e(er, c + 1), g_eTup[c], g_eTup[c + 1]);
    }
    __syncthreads();

    // ---- up, parent levels 8..1
    #pragma unroll
    for (int pl = 8; pl >= 1; --pl) {
        const int base = (1 << pl) - 1;
        const int cnt  = 1 << pl;
        for (int i = tid; i < cnt; i += NTHR) {
            int p = base + i, c = 2 * p + 1;
            A[p] = up_combine(f2add(E[c], A[c]), f2add(E[c + 1], A[c + 1]),
                              g_eTup[c], g_eTup[c + 1]);
        }
        __syncthreads();
    }

    // ---- fused: up L0 + root emit + down L1 (single thread)
    if (tid == 0) {
        float2 a0 = up_combine(f2add(E[1], A[1]), f2add(E[2], A[2]),
                               g_eTup[1], g_eTup[2]);
        emit2(orow, 0, f2add(E[0], a0));
        float2 t0 = E[0];                         // beta(root) = 0 -> t = e
        PARENT_EXP(t0, m, pd, f)
        #pragma unroll
        for (int j = 1; j <= 2; ++j) {
            float2 be = child_be(m, pd, f, g_eTdn[j]);
            emit2(orow, j, f2add(f2add(E[j], A[j]), be));
            E[j] = f2add(E[j], be);               // e -> t
        }
    }
    __syncthreads();

    // ---- down, parent levels 1..8 (parent t in E; emit children, write t)
    #pragma unroll
    for (int pl = 1; pl <= 8; ++pl) {
        const int base = (1 << pl) - 1;
        const int cnt  = 1 << pl;
        for (int i = tid; i < cnt; i += NTHR) {
            int p = base + i, c = 2 * p + 1;
            float2 tp = E[p];
            PARENT_EXP(tp, m, pd, f)
            #pragma unroll
            for (int j = 0; j < 2; ++j) {
                int n = c + j;
                float2 be = child_be(m, pd, f, g_eTdn[n]);
                emit2(orow, n, f2add(f2add(E[n], A[n]), be));
                E[n] = f2add(E[n], be);           // e -> t
            }
        }
        __syncthreads();
    }

    // ---- down leaf level fused: parents 511..1022 push t to leaves
    #pragma unroll
    for (int k = 0; k < 4; ++k) {
        int p = 511 + tid + NTHR * k;
        int c = 2 * p + 1;
        float2 tp = E[p];
        PARENT_EXP(tp, m, pd, f)
        #pragma unroll
        for (int j = 0; j < 2; ++j) {
            int n = c + j;
            float2 be = child_be(m, pd, f, g_eTdn[n]);
            emit2(orow, n, f2add(ld_e(er, n), be));   // leaf: score = e + beta
        }
    }
}

extern "C" void kernel_launch(void* const* d_in, const int* in_sizes, int n_in,
                              void* d_out, int out_size) {
    const float* em = (const float*)d_in[0];
    const float* tr = (const float*)d_in[1];
    if (n_in >= 2 && in_sizes[0] != NBATCH * 2 * NLAB) {
        em = (const float*)d_in[1];
        tr = (const float*)d_in[0];
    }
    prep_kernel<<<(NLAB + 255) / 256, 256>>>(tr);
    crf_kernel<<<NBATCH, NTHR>>>(em, (float*)d_out);
}

// round 13
// speedup vs baseline: 1.4574x; 1.1503x over previous
#include <cuda_runtime.h>

#define NLAB   2047
#define NBATCH 2048
#define NTHR   128

// Precomputed EXP of compact transition tables (gathered per launch, deterministic).
// eTup[n] = exp(transitions[parent(n), n, :, :])  (message n -> parent)
// eTdn[n] = exp(transitions[n, parent(n), :, :])  (message parent -> n)
__device__ float4 g_eTup[2048];
__device__ float4 g_eTdn[2048];

__global__ void prep_kernel(const float* __restrict__ trans) {
    int n = blockIdx.x * blockDim.x + threadIdx.x;
    if (n >= NLAB) return;
    if (n == 0) {
        g_eTup[0] = make_float4(1.f, 1.f, 1.f, 1.f);
        g_eTdn[0] = make_float4(1.f, 1.f, 1.f, 1.f);
        return;
    }
    int p = (n - 1) >> 1;
    const float4* t4 = reinterpret_cast<const float4*>(trans);
    float4 u = t4[(size_t)p * NLAB + n];
    float4 d = t4[(size_t)n * NLAB + p];
    g_eTup[n] = make_float4(__expf(u.x), __expf(u.y), __expf(u.z), __expf(u.w));
    g_eTdn[n] = make_float4(__expf(d.x), __expf(d.y), __expf(d.z), __expf(d.w));
}

__device__ __forceinline__ float2 f2add(float2 a, float2 b) {
    return make_float2(a.x + b.x, a.y + b.y);
}

// Both-destination-class logsumexp for one edge, sharing one exp.
__device__ __forceinline__ float2 lsepair2(float2 x, float4 eT) {
    float m  = fmaxf(x.x, x.y);
    float pd = __expf(fminf(x.x, x.y) - m);
    bool  f  = (x.x >= x.y);
    float a0 = f ? eT.x : eT.y, b0 = f ? eT.y : eT.x;
    float a1 = f ? eT.z : eT.w, b1 = f ? eT.w : eT.z;
    return make_float2(m + __logf(fmaf(pd, b0, a0)),
                       m + __logf(fmaf(pd, b1, a1)));
}

__device__ __forceinline__ float2 up_combine(float2 xl, float2 xr, float4 Tl, float4 Tr) {
    float2 a = lsepair2(xl, Tl);
    float2 b = lsepair2(xr, Tr);
    return make_float2(a.x + b.x, a.y + b.y);
}

__device__ __forceinline__ float lse2(float u, float v) {
    float m = fmaxf(u, v);
    return m + __logf(1.0f + __expf(fminf(u, v) - m));
}

__device__ __forceinline__ void emit2(float* __restrict__ orow, int n, float2 s) {
    float z = lse2(s.x, s.y);
    orow[n]        = s.x - z;
    orow[NLAB + n] = s.y - z;
}

__device__ __forceinline__ float2 ld_e(const float* __restrict__ er, int n) {
    return make_float2(er[n], er[NLAB + n]);
}

// shared parent-exp for both children on the way down
#define PARENT_EXP(tp, m, pd, f) \
    float m  = fmaxf((tp).x, (tp).y); \
    float pd = __expf(fminf((tp).x, (tp).y) - m); \
    bool  f  = ((tp).x >= (tp).y);

__device__ __forceinline__ float2 child_be(float m, float pd, bool f, float4 eT) {
    float a0 = f ? eT.x : eT.y, b0 = f ? eT.y : eT.x;
    float a1 = f ? eT.z : eT.w, b1 = f ? eT.w : eT.z;
    return make_float2(m + __logf(fmaf(pd, b0, a0)),
                       m + __logf(fmaf(pd, b1, a1)));
}

// TWO batch rows per 128-thread CTA. smem: E (emissions of internal nodes,
// morphing to t = e + beta in the down sweep) + A (alphas) per row = 32 KB.
// 7 CTAs/SM; grid 1024 -> 148*7 = 1036 >= 1024 -> EXACTLY ONE WAVE.
// Per-thread ILP = 2 * cnt/128 independent lse chains per phase.
__global__ void __launch_bounds__(NTHR, 7) crf_kernel(const float* __restrict__ em,
                                                      float* __restrict__ out) {
    __shared__ float2 E[2][1024], A[2][1024];

    const int tid = threadIdx.x;
    const size_t b0 = (size_t)(2 * blockIdx.x) * (2 * NLAB);
    const float* __restrict__ er0 = em + b0;
    const float* __restrict__ er1 = er0 + 2 * NLAB;
    float* __restrict__ o0 = out + b0;
    float* __restrict__ o1 = o0 + 2 * NLAB;

    // ---- load internal emissions (coalesced) + fused up leaf level:
    //      parents 511..1022 combine their two leaves (leaf alpha = 0)
    for (int n = tid; n < 1023; n += NTHR) {
        E[0][n] = ld_e(er0, n);
        E[1][n] = ld_e(er1, n);
    }
    #pragma unroll
    for (int k = 0; k < 4; ++k) {
        int p = 511 + tid + NTHR * k;
        int c = 2 * p + 1;
        float4 Tl = g_eTup[c], Tr = g_eTup[c + 1];
        A[0][p] = up_combine(ld_e(er0, c), ld_e(er0, c + 1), Tl, Tr);
        A[1][p] = up_combine(ld_e(er1, c), ld_e(er1, c + 1), Tl, Tr);
    }
    __syncthreads();

    // ---- up, parent levels 8..1 (both rows per thread -> 2x ILP)
    #pragma unroll
    for (int pl = 8; pl >= 1; --pl) {
        const int base = (1 << pl) - 1;
        const int cnt  = 1 << pl;
        #pragma unroll
        for (int k = 0; k < (cnt + NTHR - 1) / NTHR; ++k) {
            int i = tid + NTHR * k;
            if (cnt >= NTHR || i < cnt) {
                int p = base + i, c = 2 * p + 1;
                float4 Tl = g_eTup[c], Tr = g_eTup[c + 1];
                A[0][p] = up_combine(f2add(E[0][c], A[0][c]),
                                     f2add(E[0][c + 1], A[0][c + 1]), Tl, Tr);
                A[1][p] = up_combine(f2add(E[1][c], A[1][c]),
                                     f2add(E[1][c + 1], A[1][c + 1]), Tl, Tr);
            }
        }
        __syncthreads();
    }

    // ---- fused: up L0 + root emit + down L1 (one thread per row)
    if (tid < 2) {
        int r = tid;
        float* __restrict__ orow = r ? o1 : o0;
        float2 a0 = up_combine(f2add(E[r][1], A[r][1]), f2add(E[r][2], A[r][2]),
                               g_eTup[1], g_eTup[2]);
        emit2(orow, 0, f2add(E[r][0], a0));
        float2 t0 = E[r][0];                      // beta(root) = 0 -> t = e
        PARENT_EXP(t0, m, pd, f)
        #pragma unroll
        for (int j = 1; j <= 2; ++j) {
            float2 be = child_be(m, pd, f, g_eTdn[j]);
            emit2(orow, j, f2add(f2add(E[r][j], A[r][j]), be));
            E[r][j] = f2add(E[r][j], be);         // e -> t
        }
    }
    __syncthreads();

    // ---- down, parent levels 1..8 (parent t in E; emit children, write t)
    #pragma unroll
    for (int pl = 1; pl <= 8; ++pl) {
        const int base = (1 << pl) - 1;
        const int cnt  = 1 << pl;
        #pragma unroll
        for (int k = 0; k < (cnt + NTHR - 1) / NTHR; ++k) {
            int i = tid + NTHR * k;
            if (cnt >= NTHR || i < cnt) {
                int p = base + i, c = 2 * p + 1;
                float4 TL = g_eTdn[c], TR = g_eTdn[c + 1];
                #pragma unroll
                for (int r = 0; r < 2; ++r) {
                    float* __restrict__ orow = r ? o1 : o0;
                    float2 tp = E[r][p];
                    PARENT_EXP(tp, m, pd, f)
                    #pragma unroll
                    for (int j = 0; j < 2; ++j) {
                        int n = c + j;
                        float2 be = child_be(m, pd, f, j ? TR : TL);
                        emit2(orow, n, f2add(f2add(E[r][n], A[r][n]), be));
                        E[r][n] = f2add(E[r][n], be);   // e -> t
                    }
                }
            }
        }
        __syncthreads();
    }

    // ---- fused down leaf level: parents 511..1022 push t to leaves
    #pragma unroll
    for (int k = 0; k < 4; ++k) {
        int p = 511 + tid + NTHR * k;
        int c = 2 * p + 1;
        float4 TL = g_eTdn[c], TR = g_eTdn[c + 1];
        #pragma unroll
        for (int r = 0; r < 2; ++r) {
            const float* __restrict__ er = r ? er1 : er0;
            float* __restrict__ orow     = r ? o1  : o0;
            float2 tp = E[r][p];
            PARENT_EXP(tp, m, pd, f)
            #pragma unroll
            for (int j = 0; j < 2; ++j) {
                int n = c + j;
                float2 be = child_be(m, pd, f, j ? TR : TL);
                emit2(orow, n, f2add(ld_e(er, n), be));   // leaf: score = e + beta
            }
        }
    }
}

extern "C" void kernel_launch(void* const* d_in, const int* in_sizes, int n_in,
                              void* d_out, int out_size) {
    const float* em = (const float*)d_in[0];
    const float* tr = (const float*)d_in[1];
    if (n_in >= 2 && in_sizes[0] != NBATCH * 2 * NLAB) {
        em = (const float*)d_in[1];
        tr = (const float*)d_in[0];
    }
    prep_kernel<<<(NLAB + 255) / 256, 256>>>(tr);
    crf_kernel<<<NBATCH / 2, NTHR>>>(em, (float*)d_out);
}

// round 14
// speedup vs baseline: 1.6148x; 1.1080x over previous
#include <cuda_runtime.h>

#define NLAB   2047
#define NBATCH 2048
#define NTHR   256

// Precomputed EXP of compact transition tables (gathered per launch, deterministic).
// eTup[n] = exp(transitions[parent(n), n, :, :])  (message n -> parent)
// eTdn[n] = exp(transitions[n, parent(n), :, :])  (message parent -> n)
__device__ float4 g_eTup[2048];
__device__ float4 g_eTdn[2048];

__global__ void prep_kernel(const float* __restrict__ trans) {
    int n = blockIdx.x * blockDim.x + threadIdx.x;
    if (n >= NLAB) return;
    if (n == 0) {
        g_eTup[0] = make_float4(1.f, 1.f, 1.f, 1.f);
        g_eTdn[0] = make_float4(1.f, 1.f, 1.f, 1.f);
        return;
    }
    int p = (n - 1) >> 1;
    const float4* t4 = reinterpret_cast<const float4*>(trans);
    float4 u = t4[(size_t)p * NLAB + n];
    float4 d = t4[(size_t)n * NLAB + p];
    g_eTup[n] = make_float4(__expf(u.x), __expf(u.y), __expf(u.z), __expf(u.w));
    g_eTdn[n] = make_float4(__expf(d.x), __expf(d.y), __expf(d.z), __expf(d.w));
}

__device__ __forceinline__ float2 f2add(float2 a, float2 b) {
    return make_float2(a.x + b.x, a.y + b.y);
}

// Both-destination-class logsumexp for one edge, sharing one exp.
__device__ __forceinline__ float2 lsepair2(float2 x, float4 eT) {
    float m  = fmaxf(x.x, x.y);
    float pd = __expf(fminf(x.x, x.y) - m);
    bool  f  = (x.x >= x.y);
    float a0 = f ? eT.x : eT.y, b0 = f ? eT.y : eT.x;
    float a1 = f ? eT.z : eT.w, b1 = f ? eT.w : eT.z;
    return make_float2(m + __logf(fmaf(pd, b0, a0)),
                       m + __logf(fmaf(pd, b1, a1)));
}

__device__ __forceinline__ float2 up_combine(float2 xl, float2 xr, float4 Tl, float4 Tr) {
    float2 a = lsepair2(xl, Tl);
    float2 b = lsepair2(xr, Tr);
    return make_float2(a.x + b.x, a.y + b.y);
}

__device__ __forceinline__ float lse2(float u, float v) {
    float m = fmaxf(u, v);
    return m + __logf(1.0f + __expf(fminf(u, v) - m));
}

__device__ __forceinline__ void emit2(float* __restrict__ orow, int n, float2 s) {
    float z = lse2(s.x, s.y);
    orow[n]        = s.x - z;
    orow[NLAB + n] = s.y - z;
}

__device__ __forceinline__ float2 ld_e(const float* __restrict__ er, int n) {
    return make_float2(er[n], er[NLAB + n]);
}

#define PARENT_EXP(tp, m, pd, f) \
    float m  = fmaxf((tp).x, (tp).y); \
    float pd = __expf(fminf((tp).x, (tp).y) - m); \
    bool  f  = ((tp).x >= (tp).y);

__device__ __forceinline__ float2 child_be(float m, float pd, bool f, float4 eT) {
    float a0 = f ? eT.x : eT.y, b0 = f ? eT.y : eT.x;
    float a1 = f ? eT.z : eT.w, b1 = f ? eT.w : eT.z;
    return make_float2(m + __logf(fmaf(pd, b0, a0)),
                       m + __logf(fmaf(pd, b1, a1)));
}

// R5 skeleton (2 rows / 256 threads, E+A in smem) + SOFTWARE-PIPELINED table
// loads: every phase's g_eT* float4s are loaded into registers during the
// PREVIOUS phase (before its __syncthreads), so the ~250-cycle L2 latency
// overlaps compute+barrier instead of sitting in each phase's critical path.
__global__ void __launch_bounds__(NTHR, 4) crf_kernel(const float* __restrict__ em,
                                                      float* __restrict__ out) {
    __shared__ float2 E[2][1024], A[2][1024];

    const int tid = threadIdx.x;
    const size_t b0 = (size_t)(2 * blockIdx.x) * (2 * NLAB);
    const float* __restrict__ er0 = em + b0;
    const float* __restrict__ er1 = er0 + 2 * NLAB;
    float* __restrict__ o0 = out + b0;
    float* __restrict__ o1 = o0 + 2 * NLAB;

    float4 nTl, nTr;            // pipelined tables for the next phase
    float4 nDl, nDr;            // root-phase eTdn pair

    // ---- phase 0: load internal emissions + fused up leaf level
    for (int n = tid; n < 1023; n += NTHR) {
        E[0][n] = ld_e(er0, n);
        E[1][n] = ld_e(er1, n);
    }
    #pragma unroll
    for (int it = 0; it < 2; ++it) {
        int p = 511 + tid + NTHR * it;
        int c = 2 * p + 1;
        float4 Tl = g_eTup[c], Tr = g_eTup[c + 1];
        A[0][p] = up_combine(ld_e(er0, c), ld_e(er0, c + 1), Tl, Tr);
        A[1][p] = up_combine(ld_e(er1, c), ld_e(er1, c + 1), Tl, Tr);
    }
    {   // prefetch tables for up pl=8
        int c = 2 * (255 + tid) + 1;
        nTl = g_eTup[c]; nTr = g_eTup[c + 1];
    }
    __syncthreads();

    // ---- up, parent levels 8..1 (tables already in registers)
    #pragma unroll
    for (int pl = 8; pl >= 1; --pl) {
        const int base = (1 << pl) - 1;
        const int cnt  = 1 << pl;
        if (tid < cnt) {
            int p = base + tid, c = 2 * p + 1;
            A[0][p] = up_combine(f2add(E[0][c], A[0][c]),
                                 f2add(E[0][c + 1], A[0][c + 1]), nTl, nTr);
            A[1][p] = up_combine(f2add(E[1][c], A[1][c]),
                                 f2add(E[1][c + 1], A[1][c + 1]), nTl, nTr);
        }
        if (pl > 1) {           // prefetch up pl-1
            if (tid < (cnt >> 1)) {
                int c2 = 2 * ((base >> 1) + tid) + 1;
                nTl = g_eTup[c2]; nTr = g_eTup[c2 + 1];
            }
        } else {                // prefetch root-phase tables
            if (tid < 2) {
                nTl = g_eTup[1]; nTr = g_eTup[2];
                nDl = g_eTdn[1]; nDr = g_eTdn[2];
            }
        }
        __syncthreads();
    }

    // ---- root phase: up L0 + root emit + down L1 (thread r handles row r)
    if (tid < 2) {
        int r = tid;
        float* __restrict__ orow = r ? o1 : o0;
        float2 a0 = up_combine(f2add(E[r][1], A[r][1]), f2add(E[r][2], A[r][2]),
                               nTl, nTr);
        emit2(orow, 0, f2add(E[r][0], a0));
        float2 t0 = E[r][0];                       // beta(root)=0 -> t = e
        PARENT_EXP(t0, m, pd, f)
        {
            float2 be = child_be(m, pd, f, nDl);
            emit2(orow, 1, f2add(f2add(E[r][1], A[r][1]), be));
            E[r][1] = f2add(E[r][1], be);
        }
        {
            float2 be = child_be(m, pd, f, nDr);
            emit2(orow, 2, f2add(f2add(E[r][2], A[r][2]), be));
            E[r][2] = f2add(E[r][2], be);
        }
        // prefetch down pl=1 tables (parent p = 1+tid, children 2p+1, 2p+2)
        int c2 = 2 * (1 + tid) + 1;
        nTl = g_eTdn[c2]; nTr = g_eTdn[c2 + 1];
    }
    __syncthreads();

    // ---- down, parent levels 1..8
    float4 pAl, pAr, pBl, pBr;  // prefetch for the final leaf phase
    #pragma unroll
    for (int pl = 1; pl <= 8; ++pl) {
        const int base = (1 << pl) - 1;
        const int cnt  = 1 << pl;
        if (tid < cnt) {
            int p = base + tid, c = 2 * p + 1;
            #pragma unroll
            for (int r = 0; r < 2; ++r) {
                float* __restrict__ orow = r ? o1 : o0;
                float2 tp = E[r][p];
                PARENT_EXP(tp, m, pd, f)
                {
                    float2 be = child_be(m, pd, f, nTl);
                    emit2(orow, c, f2add(f2add(E[r][c], A[r][c]), be));
                    E[r][c] = f2add(E[r][c], be);
                }
                {
                    float2 be = child_be(m, pd, f, nTr);
                    emit2(orow, c + 1, f2add(f2add(E[r][c + 1], A[r][c + 1]), be));
                    E[r][c + 1] = f2add(E[r][c + 1], be);
                }
            }
        }
        if (pl < 8) {           // prefetch down pl+1
            if (tid < (cnt << 1)) {
                int c2 = 2 * (2 * base + 1 + tid) + 1;
                nTl = g_eTdn[c2]; nTr = g_eTdn[c2 + 1];
            }
        } else {                // prefetch leaf-phase tables (2 tasks/thread)
            int cA = 2 * (511 + tid) + 1;
            int cB = 2 * (511 + tid + NTHR) + 1;
            pAl = g_eTdn[cA]; pAr = g_eTdn[cA + 1];
            pBl = g_eTdn[cB]; pBr = g_eTdn[cB + 1];
        }
        __syncthreads();
    }

    // ---- fused down leaf level: parents 511..1022 push t to leaves
    #pragma unroll
    for (int it = 0; it < 2; ++it) {
        int p = 511 + tid + NTHR * it;
        int c = 2 * p + 1;
        float4 TL = it ? pBl : pAl;
        float4 TR = it ? pBr : pAr;
        #pragma unroll
        for (int r = 0; r < 2; ++r) {
            const float* __restrict__ er = r ? er1 : er0;
            float* __restrict__ orow     = r ? o1  : o0;
            float2 tp = E[r][p];
            PARENT_EXP(tp, m, pd, f)
            float2 be0 = child_be(m, pd, f, TL);
            emit2(orow, c, f2add(ld_e(er, c), be0));       // leaf: score = e + beta
            float2 be1 = child_be(m, pd, f, TR);
            emit2(orow, c + 1, f2add(ld_e(er, c + 1), be1));
        }
    }
}

extern "C" void kernel_launch(void* const* d_in, const int* in_sizes, int n_in,
                              void* d_out, int out_size) {
    const float* em = (const float*)d_in[0];
    const float* tr = (const float*)d_in[1];
    if (n_in >= 2 && in_sizes[0] != NBATCH * 2 * NLAB) {
        em = (const float*)d_in[1];
        tr = (const float*)d_in[0];
    }
    prep_kernel<<<(NLAB + 255) / 256, 256>>>(tr);
    crf_kernel<<<NBATCH / 2, NTHR>>>(em, (float*)d_out);
}

// round 16
// speedup vs baseline: 2.0157x; 1.2483x over previous
#include <cuda_runtime.h>

#define NLAB   2047
#define NBATCH 2048
#define NTHR   256

#define BAR_UP() asm volatile("bar.sync 1, 128;" ::: "memory")
#define BAR_DN() asm volatile("bar.sync 2, 128;" ::: "memory")

// Precomputed EXP of compact transition tables (gathered per launch, deterministic).
__device__ float4 g_eTup[2048];   // exp T for edge n -> parent(n)
__device__ float4 g_eTdn[2048];   // exp T for edge parent(n) -> n

__global__ void prep_kernel(const float* __restrict__ trans) {
    int n = blockIdx.x * blockDim.x + threadIdx.x;
    if (n >= NLAB) return;
    if (n == 0) {
        g_eTup[0] = make_float4(1.f, 1.f, 1.f, 1.f);
        g_eTdn[0] = make_float4(1.f, 1.f, 1.f, 1.f);
        return;
    }
    int p = (n - 1) >> 1;
    const float4* t4 = reinterpret_cast<const float4*>(trans);
    float4 u = t4[(size_t)p * NLAB + n];
    float4 d = t4[(size_t)n * NLAB + p];
    g_eTup[n] = make_float4(__expf(u.x), __expf(u.y), __expf(u.z), __expf(u.w));
    g_eTdn[n] = make_float4(__expf(d.x), __expf(d.y), __expf(d.z), __expf(d.w));
}

__device__ __forceinline__ float2 f2add(float2 a, float2 b) {
    return make_float2(a.x + b.x, a.y + b.y);
}

// Both-destination-class logsumexp for one edge, sharing one exp.
__device__ __forceinline__ float2 lsepair2(float2 x, float4 eT) {
    float m  = fmaxf(x.x, x.y);
    float pd = __expf(fminf(x.x, x.y) - m);
    bool  f  = (x.x >= x.y);
    float a0 = f ? eT.x : eT.y, b0 = f ? eT.y : eT.x;
    float a1 = f ? eT.z : eT.w, b1 = f ? eT.w : eT.z;
    return make_float2(m + __logf(fmaf(pd, b0, a0)),
                       m + __logf(fmaf(pd, b1, a1)));
}

__device__ __forceinline__ float2 up_combine(float2 xl, float2 xr, float4 Tl, float4 Tr) {
    float2 a = lsepair2(xl, Tl);
    float2 b = lsepair2(xr, Tr);
    return make_float2(a.x + b.x, a.y + b.y);
}

__device__ __forceinline__ float lse2(float u, float v) {
    float m = fmaxf(u, v);
    return m + __logf(1.0f + __expf(fminf(u, v) - m));
}

__device__ __forceinline__ void emit2(float* __restrict__ orow, int n, float2 s) {
    float z = lse2(s.x, s.y);
    orow[n]        = s.x - z;
    orow[NLAB + n] = s.y - z;
}

__device__ __forceinline__ float2 ld_e(const float* __restrict__ er, int n) {
    return make_float2(er[n], er[NLAB + n]);
}

#define PARENT_EXP(tp, m, pd, f) \
    float m  = fmaxf((tp).x, (tp).y); \
    float pd = __expf(fminf((tp).x, (tp).y) - m); \
    bool  f  = ((tp).x >= (tp).y);

__device__ __forceinline__ float2 child_be(float m, float pd, bool f, float4 eT) {
    float a0 = f ? eT.x : eT.y, b0 = f ? eT.y : eT.x;
    float a1 = f ? eT.z : eT.w, b1 = f ? eT.w : eT.z;
    return make_float2(m + __logf(fmaf(pd, b0, a0)),
                       m + __logf(fmaf(pd, b1, a1)));
}

// CONCURRENT SWEEPS: warps 0-3 compute alphas (A), warps 4-7 concurrently
// compute B = e + beta for internal nodes. The sweeps are independent; only
// the final emit needs both. Named barriers keep each team's levels ordered
// without coupling the teams. 2 rows/CTA; E/A/B = 48 KB smem.
__global__ void __launch_bounds__(NTHR, 4) crf_kernel(const float* __restrict__ em,
                                                      float* __restrict__ out) {
    __shared__ float2 E[2][1024], A[2][1024], B[2][1024];

    const int tid = threadIdx.x;
    const size_t b0 = (size_t)(2 * blockIdx.x) * (2 * NLAB);
    const float* __restrict__ er0 = em + b0;
    const float* __restrict__ er1 = er0 + 2 * NLAB;
    float* __restrict__ o0 = out + b0;
    float* __restrict__ o1 = o0 + 2 * NLAB;

    // ---- phase 0 (all threads): internal emissions, coalesced
    for (int n = tid; n < 1023; n += NTHR) {
        E[0][n] = ld_e(er0, n);
        E[1][n] = ld_e(er1, n);
    }
    __syncthreads();

    if (tid < 128) {
        // ================= UP TEAM: alphas ================================
        const int u = tid;
        // leaf-parent level: 512 parents/row, 4 iterations x 2 rows
        #pragma unroll
        for (int k = 0; k < 4; ++k) {
            int p = 511 + u + 128 * k;
            int c = 2 * p + 1;
            float4 Tl = g_eTup[c], Tr = g_eTup[c + 1];
            A[0][p] = up_combine(ld_e(er0, c), ld_e(er0, c + 1), Tl, Tr);
            A[1][p] = up_combine(ld_e(er1, c), ld_e(er1, c + 1), Tl, Tr);
        }
        // prefetch pl8 tables (2 tasks/thread)
        int c8a = 2 * (255 + u) + 1, c8b = 2 * (255 + u + 128) + 1;
        float4 Ta0 = g_eTup[c8a], Ta1 = g_eTup[c8a + 1];
        float4 Tb0 = g_eTup[c8b], Tb1 = g_eTup[c8b + 1];
        BAR_UP();
        {   // pl8: 256 parents/row
            int p = 255 + u, c = 2 * p + 1;
            A[0][p] = up_combine(f2add(E[0][c], A[0][c]),
                                 f2add(E[0][c + 1], A[0][c + 1]), Ta0, Ta1);
            A[1][p] = up_combine(f2add(E[1][c], A[1][c]),
                                 f2add(E[1][c + 1], A[1][c + 1]), Ta0, Ta1);
            p = 255 + u + 128; c = 2 * p + 1;
            A[0][p] = up_combine(f2add(E[0][c], A[0][c]),
                                 f2add(E[0][c + 1], A[0][c + 1]), Tb0, Tb1);
            A[1][p] = up_combine(f2add(E[1][c], A[1][c]),
                                 f2add(E[1][c + 1], A[1][c + 1]), Tb0, Tb1);
        }
        int c7 = 2 * (127 + u) + 1;
        float4 T70 = g_eTup[c7], T71 = g_eTup[c7 + 1];
        BAR_UP();
        {   // pl7: 128 parents/row
            int p = 127 + u, c = 2 * p + 1;
            A[0][p] = up_combine(f2add(E[0][c], A[0][c]),
                                 f2add(E[0][c + 1], A[0][c + 1]), T70, T71);
            A[1][p] = up_combine(f2add(E[1][c], A[1][c]),
                                 f2add(E[1][c + 1], A[1][c + 1]), T70, T71);
        }
        float4 nTl, nTr;
        if (u < 64) { int c6 = 2 * (63 + u) + 1; nTl = g_eTup[c6]; nTr = g_eTup[c6 + 1]; }
        BAR_UP();
        // pl 6..0
        #pragma unroll
        for (int pl = 6; pl >= 0; --pl) {
            const int base = (1 << pl) - 1;
            const int cnt  = 1 << pl;
            if (u < cnt) {
                int p = base + u, c = 2 * p + 1;
                A[0][p] = up_combine(f2add(E[0][c], A[0][c]),
                                     f2add(E[0][c + 1], A[0][c + 1]), nTl, nTr);
                A[1][p] = up_combine(f2add(E[1][c], A[1][c]),
                                     f2add(E[1][c + 1], A[1][c + 1]), nTl, nTr);
            }
            if (pl > 0 && u < (cnt >> 1)) {
                int c2 = 2 * ((base >> 1) + u) + 1;
                nTl = g_eTup[c2]; nTr = g_eTup[c2 + 1];
            }
            BAR_UP();
        }
    } else {
        // ================= DOWN TEAM: B = e + beta ========================
        const int d = tid - 128;
        if (d < 2) {           // root: beta = 0
            int r = d;
            float2 t0 = E[r][0];
            B[r][0] = t0;
            PARENT_EXP(t0, m, pd, f)
            B[r][1] = f2add(E[r][1], child_be(m, pd, f, g_eTdn[1]));
            B[r][2] = f2add(E[r][2], child_be(m, pd, f, g_eTdn[2]));
        }
        float4 nTl, nTr;
        if (d < 2) { int c = 2 * (1 + d) + 1; nTl = g_eTdn[c]; nTr = g_eTdn[c + 1]; }
        BAR_DN();
        // pl 1..6 (parents; children get B)
        #pragma unroll
        for (int pl = 1; pl <= 6; ++pl) {
            const int base = (1 << pl) - 1;
            const int cnt  = 1 << pl;
            if (d < cnt) {
                int p = base + d, c = 2 * p + 1;
                #pragma unroll
                for (int r = 0; r < 2; ++r) {
                    float2 tp = B[r][p];
                    PARENT_EXP(tp, m, pd, f)
                    B[r][c]     = f2add(E[r][c],     child_be(m, pd, f, nTl));
                    B[r][c + 1] = f2add(E[r][c + 1], child_be(m, pd, f, nTr));
                }
            }
            if (pl < 6) {
                if (d < (cnt << 1)) {
                    int c2 = 2 * (2 * base + 1 + d) + 1;
                    nTl = g_eTdn[c2]; nTr = g_eTdn[c2 + 1];
                }
            } else {
                int c2 = 2 * (127 + d) + 1;
                nTl = g_eTdn[c2]; nTr = g_eTdn[c2 + 1];
            }
            BAR_DN();
        }
        {   // pl7: 128 parents/row
            int p = 127 + d, c = 2 * p + 1;
            #pragma unroll
            for (int r = 0; r < 2; ++r) {
                float2 tp = B[r][p];
                PARENT_EXP(tp, m, pd, f)
                B[r][c]     = f2add(E[r][c],     child_be(m, pd, f, nTl));
                B[r][c + 1] = f2add(E[r][c + 1], child_be(m, pd, f, nTr));
            }
        }
        int c8a = 2 * (255 + d) + 1, c8b = 2 * (255 + d + 128) + 1;
        float4 Ta0 = g_eTdn[c8a], Ta1 = g_eTdn[c8a + 1];
        float4 Tb0 = g_eTdn[c8b], Tb1 = g_eTdn[c8b + 1];
        BAR_DN();
        {   // pl8: 256 parents/row (2 tasks/thread)
            #pragma unroll
            for (int r = 0; r < 2; ++r) {
                int p = 255 + d, c = 2 * p + 1;
                float2 tp = B[r][p];
                PARENT_EXP(tp, m, pd, f)
                B[r][c]     = f2add(E[r][c],     child_be(m, pd, f, Ta0));
                B[r][c + 1] = f2add(E[r][c + 1], child_be(m, pd, f, Ta1));
                p = 255 + d + 128; c = 2 * p + 1;
                float2 tq = B[r][p];
                PARENT_EXP(tq, m2, pd2, f2)
                B[r][c]     = f2add(E[r][c],     child_be(m2, pd2, f2, Tb0));
                B[r][c + 1] = f2add(E[r][c + 1], child_be(m2, pd2, f2, Tb1));
            }
        }
    }
    __syncthreads();

    // ================= EMIT (all 256 threads) =============================
    // internal nodes: score = B + A  (coalesced)
    #pragma unroll
    for (int k = 0; k < 4; ++k) {
        int n = tid + NTHR * k;
        if (n < 1023) {
            emit2(o0, n, f2add(B[0][n], A[0][n]));
            emit2(o1, n, f2add(B[1][n], A[1][n]));
        }
    }
    // leaves via their L9 parents (shared parent-exp; leaf alpha = 0)
    #pragma unroll
    for (int k = 0; k < 2; ++k) {
        int q = 511 + tid + NTHR * k;
        int c = 2 * q + 1;
        float4 TL = g_eTdn[c], TR = g_eTdn[c + 1];
        #pragma unroll
        for (int r = 0; r < 2; ++r) {
            const float* __restrict__ er = r ? er1 : er0;
            float* __restrict__ orow     = r ? o1  : o0;
            float2 tq = B[r][q];
            PARENT_EXP(tq, m, pd, f)
            emit2(orow, c,     f2add(ld_e(er, c),     child_be(m, pd, f, TL)));
            emit2(orow, c + 1, f2add(ld_e(er, c + 1), child_be(m, pd, f, TR)));
        }
    }
}

extern "C" void kernel_launch(void* const* d_in, const int* in_sizes, int n_in,
                              void* d_out, int out_size) {
    const float* em = (const float*)d_in[0];
    const float* tr = (const float*)d_in[1];
    if (n_in >= 2 && in_sizes[0] != NBATCH * 2 * NLAB) {
        em = (const float*)d_in[1];
        tr = (const float*)d_in[0];
    }
    prep_kernel<<<(NLAB + 255) / 256, 256>>>(tr);
    crf_kernel<<<NBATCH / 2, NTHR>>>(em, (float*)d_out);
}

// round 17
// speedup vs baseline: 2.1181x; 1.0508x over previous
#include <cuda_runtime.h>

#define NLAB   2047
#define NBATCH 2048
#define NTHR   256

#define BAR_UP() asm volatile("bar.sync 1, 128;" ::: "memory")
#define BAR_DN() asm volatile("bar.sync 2, 128;" ::: "memory")

// Precomputed EXP of compact transition tables (gathered per launch, deterministic).
__device__ float4 g_eTup[2048];   // exp T for edge n -> parent(n)
__device__ float4 g_eTdn[2048];   // exp T for edge parent(n) -> n

__global__ void prep_kernel(const float* __restrict__ trans) {
    int n = blockIdx.x * blockDim.x + threadIdx.x;
    if (n >= NLAB) return;
    if (n == 0) {
        g_eTup[0] = make_float4(1.f, 1.f, 1.f, 1.f);
        g_eTdn[0] = make_float4(1.f, 1.f, 1.f, 1.f);
        return;
    }
    int p = (n - 1) >> 1;
    const float4* t4 = reinterpret_cast<const float4*>(trans);
    float4 u = t4[(size_t)p * NLAB + n];
    float4 d = t4[(size_t)n * NLAB + p];
    g_eTup[n] = make_float4(__expf(u.x), __expf(u.y), __expf(u.z), __expf(u.w));
    g_eTdn[n] = make_float4(__expf(d.x), __expf(d.y), __expf(d.z), __expf(d.w));
}

__device__ __forceinline__ float2 f2add(float2 a, float2 b) {
    return make_float2(a.x + b.x, a.y + b.y);
}

// Both-destination-class logsumexp for one edge, sharing one exp.
__device__ __forceinline__ float2 lsepair2(float2 x, float4 eT) {
    float m  = fmaxf(x.x, x.y);
    float pd = __expf(fminf(x.x, x.y) - m);
    bool  f  = (x.x >= x.y);
    float a0 = f ? eT.x : eT.y, b0 = f ? eT.y : eT.x;
    float a1 = f ? eT.z : eT.w, b1 = f ? eT.w : eT.z;
    return make_float2(m + __logf(fmaf(pd, b0, a0)),
                       m + __logf(fmaf(pd, b1, a1)));
}

__device__ __forceinline__ float2 up_combine(float2 xl, float2 xr, float4 Tl, float4 Tr) {
    float2 a = lsepair2(xl, Tl);
    float2 b = lsepair2(xr, Tr);
    return make_float2(a.x + b.x, a.y + b.y);
}

__device__ __forceinline__ float lse2(float u, float v) {
    float m = fmaxf(u, v);
    return m + __logf(1.0f + __expf(fminf(u, v) - m));
}

__device__ __forceinline__ void emit2(float* __restrict__ orow, int n, float2 s) {
    float z = lse2(s.x, s.y);
    orow[n]        = s.x - z;
    orow[NLAB + n] = s.y - z;
}

__device__ __forceinline__ float2 ld_e(const float* __restrict__ er, int n) {
    return make_float2(er[n], er[NLAB + n]);
}

#define PARENT_EXP(tp, m, pd, f) \
    float m  = fmaxf((tp).x, (tp).y); \
    float pd = __expf(fminf((tp).x, (tp).y) - m); \
    bool  f  = ((tp).x >= (tp).y);

__device__ __forceinline__ float2 child_be(float m, float pd, bool f, float4 eT) {
    float a0 = f ? eT.x : eT.y, b0 = f ? eT.y : eT.x;
    float a1 = f ? eT.z : eT.w, b1 = f ? eT.w : eT.z;
    return make_float2(m + __logf(fmaf(pd, b0, a0)),
                       m + __logf(fmaf(pd, b1, a1)));
}

// CONCURRENT SWEEPS, REBALANCED:
//  warps 0-3 (up team):  alphas. For L9 nodes (511..1022) A holds x = e+alpha;
//                        for 0..510 A holds plain alpha.
//  warps 4-7 (down team): B = e+beta for internal nodes, THEN the whole leaf
//                        emit (it owns the hot beta values).
// E in smem only for nodes 0..510 (L9 e re-read from global where needed).
// smem = 8 + 16 + 16 = 40 KB -> 5 CTAs/SM (with regs <= 51).
__global__ void __launch_bounds__(NTHR, 5) crf_kernel(const float* __restrict__ em,
                                                      float* __restrict__ out) {
    __shared__ float2 E[2][512], A[2][1024], B[2][1024];

    const int tid = threadIdx.x;
    const size_t b0 = (size_t)(2 * blockIdx.x) * (2 * NLAB);
    const float* __restrict__ er0 = em + b0;
    const float* __restrict__ er1 = er0 + 2 * NLAB;
    float* __restrict__ o0 = out + b0;
    float* __restrict__ o1 = o0 + 2 * NLAB;

    // ---- phase 0 (all threads): emissions for nodes 0..510, coalesced
    #pragma unroll
    for (int k = 0; k < 2; ++k) {
        int n = tid + NTHR * k;
        if (n < 511) {
            E[0][n] = ld_e(er0, n);
            E[1][n] = ld_e(er1, n);
        }
    }
    __syncthreads();

    if (tid < 128) {
        // ================= UP TEAM: alphas ================================
        const int u = tid;
        // leaf-parent level: A[p] = x = e[p] + combine(leaves)
        #pragma unroll
        for (int k = 0; k < 4; ++k) {
            int p = 511 + u + 128 * k;
            int c = 2 * p + 1;
            float4 Tl = g_eTup[c], Tr = g_eTup[c + 1];
            A[0][p] = f2add(ld_e(er0, p),
                            up_combine(ld_e(er0, c), ld_e(er0, c + 1), Tl, Tr));
            A[1][p] = f2add(ld_e(er1, p),
                            up_combine(ld_e(er1, c), ld_e(er1, c + 1), Tl, Tr));
        }
        int c8a = 2 * (255 + u) + 1, c8b = 2 * (255 + u + 128) + 1;
        float4 Ta0 = g_eTup[c8a], Ta1 = g_eTup[c8a + 1];
        float4 Tb0 = g_eTup[c8b], Tb1 = g_eTup[c8b + 1];
        BAR_UP();
        {   // pl8: children hold x directly in A
            int p = 255 + u, c = 2 * p + 1;
            A[0][p] = up_combine(A[0][c], A[0][c + 1], Ta0, Ta1);
            A[1][p] = up_combine(A[1][c], A[1][c + 1], Ta0, Ta1);
            p = 255 + u + 128; c = 2 * p + 1;
            A[0][p] = up_combine(A[0][c], A[0][c + 1], Tb0, Tb1);
            A[1][p] = up_combine(A[1][c], A[1][c + 1], Tb0, Tb1);
        }
        int c7 = 2 * (127 + u) + 1;
        float4 T70 = g_eTup[c7], T71 = g_eTup[c7 + 1];
        BAR_UP();
        {   // pl7 (children 255..510: E in smem)
            int p = 127 + u, c = 2 * p + 1;
            A[0][p] = up_combine(f2add(E[0][c], A[0][c]),
                                 f2add(E[0][c + 1], A[0][c + 1]), T70, T71);
            A[1][p] = up_combine(f2add(E[1][c], A[1][c]),
                                 f2add(E[1][c + 1], A[1][c + 1]), T70, T71);
        }
        float4 nTl, nTr;
        if (u < 64) { int c6 = 2 * (63 + u) + 1; nTl = g_eTup[c6]; nTr = g_eTup[c6 + 1]; }
        BAR_UP();
        #pragma unroll
        for (int pl = 6; pl >= 0; --pl) {
            const int base = (1 << pl) - 1;
            const int cnt  = 1 << pl;
            if (u < cnt) {
                int p = base + u, c = 2 * p + 1;
                A[0][p] = up_combine(f2add(E[0][c], A[0][c]),
                                     f2add(E[0][c + 1], A[0][c + 1]), nTl, nTr);
                A[1][p] = up_combine(f2add(E[1][c], A[1][c]),
                                     f2add(E[1][c + 1], A[1][c + 1]), nTl, nTr);
            }
            if (pl > 0 && u < (cnt >> 1)) {
                int c2 = 2 * ((base >> 1) + u) + 1;
                nTl = g_eTup[c2]; nTr = g_eTup[c2 + 1];
            }
            BAR_UP();
        }
    } else {
        // ============ DOWN TEAM: B = e + beta, then leaf emit =============
        const int d = tid - 128;
        if (d < 2) {           // root: beta = 0 -> t = e
            int r = d;
            float2 t0 = E[r][0];
            B[r][0] = t0;
            PARENT_EXP(t0, m, pd, f)
            B[r][1] = f2add(E[r][1], child_be(m, pd, f, g_eTdn[1]));
            B[r][2] = f2add(E[r][2], child_be(m, pd, f, g_eTdn[2]));
        }
        float4 nTl, nTr;
        if (d < 2) { int c = 2 * (1 + d) + 1; nTl = g_eTdn[c]; nTr = g_eTdn[c + 1]; }
        BAR_DN();
        #pragma unroll
        for (int pl = 1; pl <= 6; ++pl) {
            const int base = (1 << pl) - 1;
            const int cnt  = 1 << pl;
            if (d < cnt) {
                int p = base + d, c = 2 * p + 1;
                #pragma unroll
                for (int r = 0; r < 2; ++r) {
                    float2 tp = B[r][p];
                    PARENT_EXP(tp, m, pd, f)
                    B[r][c]     = f2add(E[r][c],     child_be(m, pd, f, nTl));
                    B[r][c + 1] = f2add(E[r][c + 1], child_be(m, pd, f, nTr));
                }
            }
            if (pl < 6) {
                if (d < (cnt << 1)) {
                    int c2 = 2 * (2 * base + 1 + d) + 1;
                    nTl = g_eTdn[c2]; nTr = g_eTdn[c2 + 1];
                }
            } else {
                int c2 = 2 * (127 + d) + 1;
                nTl = g_eTdn[c2]; nTr = g_eTdn[c2 + 1];
            }
            BAR_DN();
        }
        {   // pl7 (children 255..510: E in smem)
            int p = 127 + d, c = 2 * p + 1;
            #pragma unroll
            for (int r = 0; r < 2; ++r) {
                float2 tp = B[r][p];
                PARENT_EXP(tp, m, pd, f)
                B[r][c]     = f2add(E[r][c],     child_be(m, pd, f, nTl));
                B[r][c + 1] = f2add(E[r][c + 1], child_be(m, pd, f, nTr));
            }
        }
        int c8a = 2 * (255 + d) + 1, c8b = 2 * (255 + d + 128) + 1;
        float4 Ta0 = g_eTdn[c8a], Ta1 = g_eTdn[c8a + 1];
        float4 Tb0 = g_eTdn[c8b], Tb1 = g_eTdn[c8b + 1];
        BAR_DN();
        {   // pl8: children 511..1022 -> e from GLOBAL (not in smem)
            #pragma unroll
            for (int r = 0; r < 2; ++r) {
                const float* __restrict__ er = r ? er1 : er0;
                int p = 255 + d, c = 2 * p + 1;
                float2 tp = B[r][p];
                PARENT_EXP(tp, m, pd, f)
                B[r][c]     = f2add(ld_e(er, c),     child_be(m, pd, f, Ta0));
                B[r][c + 1] = f2add(ld_e(er, c + 1), child_be(m, pd, f, Ta1));
                p = 255 + d + 128; c = 2 * p + 1;
                float2 tq = B[r][p];
                PARENT_EXP(tq, m2, pd2, f2)
                B[r][c]     = f2add(ld_e(er, c),     child_be(m2, pd2, f2, Tb0));
                B[r][c + 1] = f2add(ld_e(er, c + 1), child_be(m2, pd2, f2, Tb1));
            }
        }
        BAR_DN();
        // ---- leaf emit (down team owns hot betas): q = 511..1022
        #pragma unroll
        for (int k = 0; k < 4; ++k) {
            int q = 511 + d + 128 * k;
            int c = 2 * q + 1;
            float4 TL = g_eTdn[c], TR = g_eTdn[c + 1];
            #pragma unroll
            for (int r = 0; r < 2; ++r) {
                const float* __restrict__ er = r ? er1 : er0;
                float* __restrict__ orow     = r ? o1  : o0;
                float2 tq = B[r][q];
                PARENT_EXP(tq, m, pd, f)
                emit2(orow, c,     f2add(ld_e(er, c),     child_be(m, pd, f, TL)));
                emit2(orow, c + 1, f2add(ld_e(er, c + 1), child_be(m, pd, f, TR)));
            }
        }
    }
    __syncthreads();

    // ================= EMIT internal nodes (all 256 threads) ==============
    // 0..510:    score = B + A              (B = e+beta, A = alpha)
    // 511..1022: score = A + B - e_global   (A = e+alpha, B = e+beta)
    #pragma unroll
    for (int k = 0; k < 4; ++k) {
        int n = tid + NTHR * k;
        if (n < 511) {
            emit2(o0, n, f2add(B[0][n], A[0][n]));
            emit2(o1, n, f2add(B[1][n], A[1][n]));
        } else if (n < 1023) {
            float2 s0 = f2add(A[0][n], B[0][n]);
            float2 e0 = ld_e(er0, n);
            emit2(o0, n, make_float2(s0.x - e0.x, s0.y - e0.y));
            float2 s1 = f2add(A[1][n], B[1][n]);
            float2 e1 = ld_e(er1, n);
            emit2(o1, n, make_float2(s1.x - e1.x, s1.y - e1.y));
        }
    }
}

extern "C" void kernel_launch(void* const* d_in, const int* in_sizes, int n_in,
                              void* d_out, int out_size) {
    const float* em = (const float*)d_in[0];
    const float* tr = (const float*)d_in[1];
    if (n_in >= 2 && in_sizes[0] != NBATCH * 2 * NLAB) {
        em = (const float*)d_in[1];
        tr = (const float*)d_in[0];
    }
    prep_kernel<<<(NLAB + 255) / 256, 256>>>(tr);
    crf_kernel<<<NBATCH / 2, NTHR>>>(em, (float*)d_out);
}